// round 5
// baseline (speedup 1.0000x reference)
#include <cuda_runtime.h>
#include <math.h>

#define BATCH 8
#define SEQ   2048
#define DIM   1024
#define MTOT  (BATCH*SEQ)          // 16384

#define NEGVAL (-4294967295.0f)    // -(2^32)+1 rounded to fp32, same as jnp.float32

// ---------------- scratch (device globals; no allocation) ----------------
__device__ float g_q[(size_t)MTOT * DIM];      // 64 MB
__device__ float g_k[(size_t)MTOT * DIM];      // 64 MB
__device__ float g_v[(size_t)MTOT * DIM];      // 64 MB
__device__ float g_attn[(size_t)BATCH * SEQ * SEQ]; // 128 MB
__device__ float g_mask[MTOT];

// ---------------- SGEMM tile config ----------------
#define BM 128
#define BN 128
#define BK 8
#define SPAD 132   // padded smem row length (kills store bank conflicts)

// Double-buffered 128x128x8 register-blocked SGEMM mainloop.
// A: row-major [*, K] starting at row `rowBase`.
// If TRANSB==false: Bm is row-major [K, ldb] (ldb = N row stride), tile cols at colBase.
// If TRANSB==true : Bm is row-major [N, K]; logical B[k][n] = Bm[n*K + k].
template<bool TRANSB>
__device__ __forceinline__ void sgemm_body(
    const float* __restrict__ A, const float* __restrict__ Bm,
    int K, int ldb, int rowBase, int colBase, float (&acc)[8][8])
{
    __shared__ float As[2][BK][SPAD];
    __shared__ float Bs[2][BK][SPAD];

    const int tid  = threadIdx.x;
    const int tcol = tid & 15;   // 0..15
    const int trow = tid >> 4;   // 0..15
    const int aRow = tid >> 1;        // 0..127
    const int aCol = (tid & 1) * 4;   // 0 or 4
    const int bRow = tid >> 5;        // 0..7   (!TRANSB path)
    const int bCol = (tid & 31) * 4;  // 0..124

    // ---- prologue: load tile 0 into buffer 0 ----
    {
        float4 a4 = *(const float4*)(A + (size_t)(rowBase + aRow) * K + aCol);
        As[0][aCol + 0][aRow] = a4.x;
        As[0][aCol + 1][aRow] = a4.y;
        As[0][aCol + 2][aRow] = a4.z;
        As[0][aCol + 3][aRow] = a4.w;
        if (!TRANSB) {
            float4 b4 = *(const float4*)(Bm + (size_t)bRow * ldb + (colBase + bCol));
            *(float4*)&Bs[0][bRow][bCol] = b4;
        } else {
            float4 b4 = *(const float4*)(Bm + (size_t)(colBase + aRow) * K + aCol);
            Bs[0][aCol + 0][aRow] = b4.x;
            Bs[0][aCol + 1][aRow] = b4.y;
            Bs[0][aCol + 2][aRow] = b4.z;
            Bs[0][aCol + 3][aRow] = b4.w;
        }
    }
    __syncthreads();

    int buf = 0;
    for (int k0 = 0; k0 < K; k0 += BK) {
        const bool has_next = (k0 + BK) < K;
        float4 pa, pb;
        if (has_next) {
            const int kn = k0 + BK;
            pa = *(const float4*)(A + (size_t)(rowBase + aRow) * K + (kn + aCol));
            if (!TRANSB) {
                pb = *(const float4*)(Bm + (size_t)(kn + bRow) * ldb + (colBase + bCol));
            } else {
                pb = *(const float4*)(Bm + (size_t)(colBase + aRow) * K + (kn + aCol));
            }
        }

        #pragma unroll
        for (int kk = 0; kk < BK; kk++) {
            float4 a0 = *(const float4*)&As[buf][kk][trow * 8];
            float4 a1 = *(const float4*)&As[buf][kk][trow * 8 + 4];
            float4 b0 = *(const float4*)&Bs[buf][kk][tcol * 8];
            float4 b1 = *(const float4*)&Bs[buf][kk][tcol * 8 + 4];
            float ar[8] = {a0.x, a0.y, a0.z, a0.w, a1.x, a1.y, a1.z, a1.w};
            float br[8] = {b0.x, b0.y, b0.z, b0.w, b1.x, b1.y, b1.z, b1.w};
            #pragma unroll
            for (int i = 0; i < 8; i++)
                #pragma unroll
                for (int j = 0; j < 8; j++)
                    acc[i][j] += ar[i] * br[j];
        }

        if (has_next) {
            const int nb = buf ^ 1;
            As[nb][aCol + 0][aRow] = pa.x;
            As[nb][aCol + 1][aRow] = pa.y;
            As[nb][aCol + 2][aRow] = pa.z;
            As[nb][aCol + 3][aRow] = pa.w;
            if (!TRANSB) {
                *(float4*)&Bs[nb][bRow][bCol] = pb;
            } else {
                Bs[nb][aCol + 0][aRow] = pb.x;
                Bs[nb][aCol + 1][aRow] = pb.y;
                Bs[nb][aCol + 2][aRow] = pb.z;
                Bs[nb][aCol + 3][aRow] = pb.w;
            }
            __syncthreads();
            buf = nb;
        }
    }
}

// ---------------- masks: sin(|sum(x, -1)|) ----------------
__global__ void mask_kernel(const float* __restrict__ x)
{
    const int row = blockIdx.x;              // 0..MTOT-1
    const float* xr = x + (size_t)row * DIM;
    float s = 0.f;
    for (int i = threadIdx.x; i < DIM; i += 256) s += xr[i];

    __shared__ float red[8];
    #pragma unroll
    for (int o = 16; o > 0; o >>= 1) s += __shfl_xor_sync(0xffffffffu, s, o);
    if ((threadIdx.x & 31) == 0) red[threadIdx.x >> 5] = s;
    __syncthreads();
    if (threadIdx.x == 0) {
        float v = 0.f;
        #pragma unroll
        for (int w = 0; w < 8; w++) v += red[w];
        g_mask[row] = sinf(fabsf(v));
    }
}

// ---------------- QKV: relu(x @ W + b), z selects q/k/v ----------------
__global__ void __launch_bounds__(256, 2) qkv_kernel(
    const float* __restrict__ x,
    const float* __restrict__ Wq, const float* __restrict__ bq,
    const float* __restrict__ Wk, const float* __restrict__ bk,
    const float* __restrict__ Wv, const float* __restrict__ bv)
{
    const float* W; const float* bias; float* out;
    if (blockIdx.z == 0)      { W = Wq; bias = bq; out = g_q; }
    else if (blockIdx.z == 1) { W = Wk; bias = bk; out = g_k; }
    else                      { W = Wv; bias = bv; out = g_v; }

    const int rowBase = blockIdx.y * BM;
    const int colBase = blockIdx.x * BN;

    float acc[8][8] = {};
    sgemm_body<false>(x, W, DIM, DIM, rowBase, colBase, acc);

    const int tcol = threadIdx.x & 15;
    const int trow = threadIdx.x >> 4;
    const int col0 = colBase + tcol * 8;
    float4 bb0 = *(const float4*)(bias + col0);
    float4 bb1 = *(const float4*)(bias + col0 + 4);
    const float bv8[8] = {bb0.x, bb0.y, bb0.z, bb0.w, bb1.x, bb1.y, bb1.z, bb1.w};

    #pragma unroll
    for (int i = 0; i < 8; i++) {
        const int row = rowBase + trow * 8 + i;
        float4 v0, v1;
        v0.x = fmaxf(acc[i][0] + bv8[0], 0.f);
        v0.y = fmaxf(acc[i][1] + bv8[1], 0.f);
        v0.z = fmaxf(acc[i][2] + bv8[2], 0.f);
        v0.w = fmaxf(acc[i][3] + bv8[3], 0.f);
        v1.x = fmaxf(acc[i][4] + bv8[4], 0.f);
        v1.y = fmaxf(acc[i][5] + bv8[5], 0.f);
        v1.z = fmaxf(acc[i][6] + bv8[6], 0.f);
        v1.w = fmaxf(acc[i][7] + bv8[7], 0.f);
        *(float4*)(out + (size_t)row * DIM + col0)     = v0;
        *(float4*)(out + (size_t)row * DIM + col0 + 4) = v1;
    }
}

// ---------------- scores: (q @ k^T) / 32, key-masked ----------------
__global__ void __launch_bounds__(256, 2) scores_kernel()
{
    const int b = blockIdx.z;
    const float* A  = g_q + (size_t)b * SEQ * DIM;
    const float* Kp = g_k + (size_t)b * SEQ * DIM;
    float* C = g_attn + (size_t)b * SEQ * SEQ;

    const int rowBase = blockIdx.y * BM;
    const int colBase = blockIdx.x * BN;

    float acc[8][8] = {};
    sgemm_body<true>(A, Kp, DIM, DIM, rowBase, colBase, acc);

    const int tcol = threadIdx.x & 15;
    const int trow = threadIdx.x >> 4;
    const int col0 = colBase + tcol * 8;

    float mk[8];
    #pragma unroll
    for (int j = 0; j < 8; j++) mk[j] = g_mask[b * SEQ + col0 + j];

    #pragma unroll
    for (int i = 0; i < 8; i++) {
        const int row = rowBase + trow * 8 + i;
        float o[8];
        #pragma unroll
        for (int j = 0; j < 8; j++) {
            float val = acc[i][j] * 0.03125f;   // 1/sqrt(1024)
            o[j] = (mk[j] == 0.0f) ? NEGVAL : val;
        }
        *(float4*)(C + (size_t)row * SEQ + col0)     = make_float4(o[0], o[1], o[2], o[3]);
        *(float4*)(C + (size_t)row * SEQ + col0 + 4) = make_float4(o[4], o[5], o[6], o[7]);
    }
}

// ---------------- softmax over keys + post-softmax query-mask scale ----------------
__global__ void softmax_kernel()
{
    const int row = blockIdx.x;       // b*SEQ + q
    float* sr = g_attn + (size_t)row * SEQ;
    const int t = threadIdx.x;

    float r[8];
    float mx = -INFINITY;
    #pragma unroll
    for (int i = 0; i < 8; i++) {
        r[i] = sr[t + i * 256];
        mx = fmaxf(mx, r[i]);
    }

    __shared__ float red[8];
    __shared__ float smax, ssum;

    #pragma unroll
    for (int o = 16; o > 0; o >>= 1) mx = fmaxf(mx, __shfl_xor_sync(0xffffffffu, mx, o));
    if ((t & 31) == 0) red[t >> 5] = mx;
    __syncthreads();
    if (t == 0) {
        float v = red[0];
        #pragma unroll
        for (int w = 1; w < 8; w++) v = fmaxf(v, red[w]);
        smax = v;
    }
    __syncthreads();
    const float rowmax = smax;

    float sum = 0.f;
    #pragma unroll
    for (int i = 0; i < 8; i++) {
        r[i] = expf(r[i] - rowmax);
        sum += r[i];
    }
    #pragma unroll
    for (int o = 16; o > 0; o >>= 1) sum += __shfl_xor_sync(0xffffffffu, sum, o);
    __syncthreads();   // protect red[] reuse
    if ((t & 31) == 0) red[t >> 5] = sum;
    __syncthreads();
    if (t == 0) {
        float v = 0.f;
        #pragma unroll
        for (int w = 0; w < 8; w++) v += red[w];
        ssum = v;
    }
    __syncthreads();

    const float scale = g_mask[row] / ssum;  // softmax normalize * query-mask value
    #pragma unroll
    for (int i = 0; i < 8; i++) sr[t + i * 256] = r[i] * scale;
}

// ---------------- out = attn @ v + q ----------------
__global__ void __launch_bounds__(256, 2) out_kernel(float* __restrict__ outp)
{
    const int b = blockIdx.z;
    const float* A  = g_attn + (size_t)b * SEQ * SEQ;   // [SEQ, SEQ]
    const float* Bv = g_v    + (size_t)b * SEQ * DIM;   // [SEQ, DIM]
    const float* Q  = g_q    + (size_t)b * SEQ * DIM;
    float* C = outp + (size_t)b * SEQ * DIM;

    const int rowBase = blockIdx.y * BM;
    const int colBase = blockIdx.x * BN;

    float acc[8][8] = {};
    sgemm_body<false>(A, Bv, SEQ, DIM, rowBase, colBase, acc);

    const int tcol = threadIdx.x & 15;
    const int trow = threadIdx.x >> 4;
    const int col0 = colBase + tcol * 8;

    #pragma unroll
    for (int i = 0; i < 8; i++) {
        const int row = rowBase + trow * 8 + i;
        float4 q0 = *(const float4*)(Q + (size_t)row * DIM + col0);
        float4 q1 = *(const float4*)(Q + (size_t)row * DIM + col0 + 4);
        float4 v0 = make_float4(acc[i][0] + q0.x, acc[i][1] + q0.y,
                                acc[i][2] + q0.z, acc[i][3] + q0.w);
        float4 v1 = make_float4(acc[i][4] + q1.x, acc[i][5] + q1.y,
                                acc[i][6] + q1.z, acc[i][7] + q1.w);
        *(float4*)(C + (size_t)row * DIM + col0)     = v0;
        *(float4*)(C + (size_t)row * DIM + col0 + 4) = v1;
    }
}

// ---------------- launch ----------------
extern "C" void kernel_launch(void* const* d_in, const int* in_sizes, int n_in,
                              void* d_out, int out_size)
{
    const float* x  = (const float*)d_in[0];
    const float* Wq = (const float*)d_in[1];
    const float* bq = (const float*)d_in[2];
    const float* Wk = (const float*)d_in[3];
    const float* bk = (const float*)d_in[4];
    const float* Wv = (const float*)d_in[5];
    const float* bv = (const float*)d_in[6];
    float* outp = (float*)d_out;

    // 1. masks
    mask_kernel<<<MTOT, 256>>>(x);

    // 2. QKV projections (z = q/k/v)
    {
        dim3 grid(DIM / BN, MTOT / BM, 3);
        qkv_kernel<<<grid, 256>>>(x, Wq, bq, Wk, bk, Wv, bv);
    }

    // 3. scores = q k^T / 32, key-masked
    {
        dim3 grid(SEQ / BN, SEQ / BM, BATCH);
        scores_kernel<<<grid, 256>>>();
    }

    // 4. softmax + query-mask scaling
    softmax_kernel<<<MTOT, 256>>>();

    // 5. out = attn v + q
    {
        dim3 grid(DIM / BN, SEQ / BM, BATCH);
        out_kernel<<<grid, 256>>>(outp);
    }
}

// round 6
// speedup vs baseline: 2.0916x; 2.0916x over previous
#include <cuda_runtime.h>
#include <math.h>
#include <stdint.h>

#define BATCH 8
#define SEQ   2048
#define DIM   1024
#define MTOT  (BATCH*SEQ)          // 16384

#define NEGVAL (-4294967295.0f)    // -(2^32)+1 rounded to fp32, same as jnp.float32

// ---------------- scratch (device globals; no allocation) ----------------
__device__ float g_q[(size_t)MTOT * DIM];      // 64 MB
__device__ float g_k[(size_t)MTOT * DIM];      // 64 MB
__device__ float g_v[(size_t)MTOT * DIM];      // 64 MB
__device__ float g_attn[(size_t)BATCH * SEQ * SEQ]; // 128 MB
__device__ float g_mask[MTOT];

// ---------------- TF32 MMA tile config ----------------
// Block tile 128x128x16, 256 threads = 8 warps, warp tile 64x32.
// Warp does 4 (m16) x 4 (n8) mma.m16n8k8 per 8-wide k-step, 2 k-steps per tile.
#define BM 128
#define BN 128
#define BKT 16
#define SROW 136   // smem row stride (floats): 8*tig + gid + c covers all 32 banks -> conflict-free frags

__device__ __forceinline__ float to_tf32(float x) {
    uint32_t r;
    asm("cvt.rna.tf32.f32 %0, %1;" : "=r"(r) : "f"(x));
    return __uint_as_float(r);
}

#define MMA_TF32(d0,d1,d2,d3,a0,a1,a2,a3,b0,b1)                                          \
    asm volatile("mma.sync.aligned.m16n8k8.row.col.f32.tf32.tf32.f32 "                   \
                 "{%0,%1,%2,%3},{%4,%5,%6,%7},{%8,%9},{%0,%1,%2,%3};"                    \
                 : "+f"(d0), "+f"(d1), "+f"(d2), "+f"(d3)                                 \
                 : "r"(a0), "r"(a1), "r"(a2), "r"(a3), "r"(b0), "r"(b1))

// Generic double-buffered TF32 MMA mainloop.
// A: row-major [*, K] starting at rowBase (tile rows 128).
// TRANSB==false: Bm row-major [K, ldb], tile cols at colBase.
// TRANSB==true : Bm row-major [N, K]; logical B[k][n] = Bm[n*K + k].
// acc[mt][nt][4] per-thread fragments (m16n8 layout).
template<bool TRANSB>
__device__ __forceinline__ void mma_body(
    const float* __restrict__ A, const float* __restrict__ Bm,
    int K, int ldb, int rowBase, int colBase, float (&acc)[4][4][4])
{
    __shared__ float As[2][BKT][SROW];
    __shared__ float Bs[2][BKT][SROW];

    const int tid  = threadIdx.x;
    const int lane = tid & 31;
    const int wid  = tid >> 5;
    const int gid  = lane >> 2;   // 0..7
    const int tig  = lane & 3;    // 0..3
    const int wm   = (wid & 1) * 64;   // warp row offset
    const int wn   = (wid >> 1) * 32;  // warp col offset

    // A loader (transpose k-major into smem): row lr, two float4 at k = lkv*4 and lkv*4+8
    const int lr  = tid & 127;
    const int lkv = tid >> 7;     // 0/1
    // B loader (!TRANSB): rows bk and bk+8, float4 at col bn
    const int bk  = tid >> 5;     // 0..7
    const int bn  = (tid & 31) * 4;

    // ---- register staging + store helpers ----
    float4 pa0, pa1, pb0, pb1;

    auto load_regs = [&](int k0) {
        const float* aBase = A + (size_t)(rowBase + lr) * K + k0;
        pa0 = *(const float4*)(aBase + lkv * 4);
        pa1 = *(const float4*)(aBase + lkv * 4 + 8);
        if (!TRANSB) {
            const float* bBase = Bm + (size_t)(k0 + bk) * ldb + colBase + bn;
            pb0 = *(const float4*)(bBase);
            pb1 = *(const float4*)(bBase + (size_t)8 * ldb);
        } else {
            const float* bBase = Bm + (size_t)(colBase + lr) * K + k0;
            pb0 = *(const float4*)(bBase + lkv * 4);
            pb1 = *(const float4*)(bBase + lkv * 4 + 8);
        }
    };

    auto store_smem = [&](int buf) {
        // A: transpose into As[k][m]
        As[buf][lkv * 4 + 0][lr] = to_tf32(pa0.x);
        As[buf][lkv * 4 + 1][lr] = to_tf32(pa0.y);
        As[buf][lkv * 4 + 2][lr] = to_tf32(pa0.z);
        As[buf][lkv * 4 + 3][lr] = to_tf32(pa0.w);
        As[buf][lkv * 4 + 8][lr] = to_tf32(pa1.x);
        As[buf][lkv * 4 + 9][lr] = to_tf32(pa1.y);
        As[buf][lkv * 4 +10][lr] = to_tf32(pa1.z);
        As[buf][lkv * 4 +11][lr] = to_tf32(pa1.w);
        if (!TRANSB) {
            float4 c0 = make_float4(to_tf32(pb0.x), to_tf32(pb0.y), to_tf32(pb0.z), to_tf32(pb0.w));
            float4 c1 = make_float4(to_tf32(pb1.x), to_tf32(pb1.y), to_tf32(pb1.z), to_tf32(pb1.w));
            *(float4*)&Bs[buf][bk][bn]     = c0;
            *(float4*)&Bs[buf][bk + 8][bn] = c1;
        } else {
            Bs[buf][lkv * 4 + 0][lr] = to_tf32(pb0.x);
            Bs[buf][lkv * 4 + 1][lr] = to_tf32(pb0.y);
            Bs[buf][lkv * 4 + 2][lr] = to_tf32(pb0.z);
            Bs[buf][lkv * 4 + 3][lr] = to_tf32(pb0.w);
            Bs[buf][lkv * 4 + 8][lr] = to_tf32(pb1.x);
            Bs[buf][lkv * 4 + 9][lr] = to_tf32(pb1.y);
            Bs[buf][lkv * 4 +10][lr] = to_tf32(pb1.z);
            Bs[buf][lkv * 4 +11][lr] = to_tf32(pb1.w);
        }
    };

    // ---- prologue ----
    load_regs(0);
    store_smem(0);
    __syncthreads();

    const int nTiles = K / BKT;
    int buf = 0;

    for (int t = 0; t < nTiles; t++) {
        const bool has_next = (t + 1) < nTiles;
        if (has_next) load_regs((t + 1) * BKT);

        // compute 2 k-steps of 8 on buffer `buf`
        #pragma unroll
        for (int ks = 0; ks < 2; ks++) {
            const int k0 = ks * 8;
            uint32_t af[4][4], bf[4][2];
            #pragma unroll
            for (int mt = 0; mt < 4; mt++) {
                const int m0 = wm + mt * 16;
                af[mt][0] = __float_as_uint(As[buf][k0 + tig    ][m0 + gid    ]);
                af[mt][1] = __float_as_uint(As[buf][k0 + tig    ][m0 + gid + 8]);
                af[mt][2] = __float_as_uint(As[buf][k0 + tig + 4][m0 + gid    ]);
                af[mt][3] = __float_as_uint(As[buf][k0 + tig + 4][m0 + gid + 8]);
            }
            #pragma unroll
            for (int nt = 0; nt < 4; nt++) {
                const int n0 = wn + nt * 8;
                bf[nt][0] = __float_as_uint(Bs[buf][k0 + tig    ][n0 + gid]);
                bf[nt][1] = __float_as_uint(Bs[buf][k0 + tig + 4][n0 + gid]);
            }
            #pragma unroll
            for (int mt = 0; mt < 4; mt++)
                #pragma unroll
                for (int nt = 0; nt < 4; nt++)
                    MMA_TF32(acc[mt][nt][0], acc[mt][nt][1], acc[mt][nt][2], acc[mt][nt][3],
                             af[mt][0], af[mt][1], af[mt][2], af[mt][3],
                             bf[nt][0], bf[nt][1]);
        }

        if (has_next) {
            store_smem(buf ^ 1);
            __syncthreads();
            buf ^= 1;
        }
    }
}

// Fragment -> (row, col) map used by all epilogues:
// row0 = rowBase + wm + mt*16 + gid ; row1 = row0 + 8
// col  = colBase + wn + nt*8 + 2*tig  (c0,c1 = col, col+1 ; c2,c3 same cols at row1)

// ---------------- masks: sin(|sum(x, -1)|) ----------------
__global__ void mask_kernel(const float* __restrict__ x)
{
    const int row = blockIdx.x;
    const float* xr = x + (size_t)row * DIM;
    float s = 0.f;
    for (int i = threadIdx.x; i < DIM; i += 256) s += xr[i];

    __shared__ float red[8];
    #pragma unroll
    for (int o = 16; o > 0; o >>= 1) s += __shfl_xor_sync(0xffffffffu, s, o);
    if ((threadIdx.x & 31) == 0) red[threadIdx.x >> 5] = s;
    __syncthreads();
    if (threadIdx.x == 0) {
        float v = 0.f;
        #pragma unroll
        for (int w = 0; w < 8; w++) v += red[w];
        g_mask[row] = sinf(fabsf(v));
    }
}

// ---------------- QKV: relu(x @ W + b) ----------------
__global__ void __launch_bounds__(256, 2) qkv_kernel(
    const float* __restrict__ x,
    const float* __restrict__ Wq, const float* __restrict__ bq,
    const float* __restrict__ Wk, const float* __restrict__ bk,
    const float* __restrict__ Wv, const float* __restrict__ bv)
{
    const float* W; const float* bias; float* out;
    if (blockIdx.z == 0)      { W = Wq; bias = bq; out = g_q; }
    else if (blockIdx.z == 1) { W = Wk; bias = bk; out = g_k; }
    else                      { W = Wv; bias = bv; out = g_v; }

    const int rowBase = blockIdx.y * BM;
    const int colBase = blockIdx.x * BN;

    float acc[4][4][4] = {};
    mma_body<false>(x, W, DIM, DIM, rowBase, colBase, acc);

    const int lane = threadIdx.x & 31;
    const int wid  = threadIdx.x >> 5;
    const int gid  = lane >> 2, tig = lane & 3;
    const int wm   = (wid & 1) * 64, wn = (wid >> 1) * 32;

    #pragma unroll
    for (int nt = 0; nt < 4; nt++) {
        const int col = colBase + wn + nt * 8 + 2 * tig;
        const float b0 = bias[col], b1 = bias[col + 1];
        #pragma unroll
        for (int mt = 0; mt < 4; mt++) {
            const int row0 = rowBase + wm + mt * 16 + gid;
            float2 v0 = make_float2(fmaxf(acc[mt][nt][0] + b0, 0.f),
                                    fmaxf(acc[mt][nt][1] + b1, 0.f));
            float2 v1 = make_float2(fmaxf(acc[mt][nt][2] + b0, 0.f),
                                    fmaxf(acc[mt][nt][3] + b1, 0.f));
            *(float2*)(out + (size_t)row0 * DIM + col)       = v0;
            *(float2*)(out + (size_t)(row0 + 8) * DIM + col) = v1;
        }
    }
}

// ---------------- scores: (q @ k^T) / 32, key-masked ----------------
__global__ void __launch_bounds__(256, 2) scores_kernel()
{
    const int b = blockIdx.z;
    const float* A  = g_q + (size_t)b * SEQ * DIM;
    const float* Kp = g_k + (size_t)b * SEQ * DIM;
    float* C = g_attn + (size_t)b * SEQ * SEQ;

    const int rowBase = blockIdx.y * BM;
    const int colBase = blockIdx.x * BN;

    float acc[4][4][4] = {};
    mma_body<true>(A, Kp, DIM, DIM, rowBase, colBase, acc);

    const int lane = threadIdx.x & 31;
    const int wid  = threadIdx.x >> 5;
    const int gid  = lane >> 2, tig = lane & 3;
    const int wm   = (wid & 1) * 64, wn = (wid >> 1) * 32;

    #pragma unroll
    for (int nt = 0; nt < 4; nt++) {
        const int col = colBase + wn + nt * 8 + 2 * tig;
        const float m0 = g_mask[b * SEQ + col];
        const float m1 = g_mask[b * SEQ + col + 1];
        #pragma unroll
        for (int mt = 0; mt < 4; mt++) {
            const int row0 = rowBase + wm + mt * 16 + gid;
            float2 v0, v1;
            v0.x = (m0 == 0.f) ? NEGVAL : acc[mt][nt][0] * 0.03125f;
            v0.y = (m1 == 0.f) ? NEGVAL : acc[mt][nt][1] * 0.03125f;
            v1.x = (m0 == 0.f) ? NEGVAL : acc[mt][nt][2] * 0.03125f;
            v1.y = (m1 == 0.f) ? NEGVAL : acc[mt][nt][3] * 0.03125f;
            *(float2*)(C + (size_t)row0 * SEQ + col)       = v0;
            *(float2*)(C + (size_t)(row0 + 8) * SEQ + col) = v1;
        }
    }
}

// ---------------- softmax over keys + post-softmax query-mask scale ----------------
__global__ void softmax_kernel()
{
    const int row = blockIdx.x;
    float* sr = g_attn + (size_t)row * SEQ;
    const int t = threadIdx.x;

    float r[8];
    float mx = -INFINITY;
    #pragma unroll
    for (int i = 0; i < 8; i++) {
        r[i] = sr[t + i * 256];
        mx = fmaxf(mx, r[i]);
    }

    __shared__ float red[8];
    __shared__ float smax, ssum;

    #pragma unroll
    for (int o = 16; o > 0; o >>= 1) mx = fmaxf(mx, __shfl_xor_sync(0xffffffffu, mx, o));
    if ((t & 31) == 0) red[t >> 5] = mx;
    __syncthreads();
    if (t == 0) {
        float v = red[0];
        #pragma unroll
        for (int w = 1; w < 8; w++) v = fmaxf(v, red[w]);
        smax = v;
    }
    __syncthreads();
    const float rowmax = smax;

    float sum = 0.f;
    #pragma unroll
    for (int i = 0; i < 8; i++) {
        r[i] = expf(r[i] - rowmax);
        sum += r[i];
    }
    #pragma unroll
    for (int o = 16; o > 0; o >>= 1) sum += __shfl_xor_sync(0xffffffffu, sum, o);
    __syncthreads();
    if ((t & 31) == 0) red[t >> 5] = sum;
    __syncthreads();
    if (t == 0) {
        float v = 0.f;
        #pragma unroll
        for (int w = 0; w < 8; w++) v += red[w];
        ssum = v;
    }
    __syncthreads();

    const float scale = g_mask[row] / ssum;
    #pragma unroll
    for (int i = 0; i < 8; i++) sr[t + i * 256] = r[i] * scale;
}

// ---------------- out = attn @ v + q ----------------
__global__ void __launch_bounds__(256, 2) out_kernel(float* __restrict__ outp)
{
    const int b = blockIdx.z;
    const float* A  = g_attn + (size_t)b * SEQ * SEQ;
    const float* Bv = g_v    + (size_t)b * SEQ * DIM;
    const float* Q  = g_q    + (size_t)b * SEQ * DIM;
    float* C = outp + (size_t)b * SEQ * DIM;

    const int rowBase = blockIdx.y * BM;
    const int colBase = blockIdx.x * BN;

    float acc[4][4][4] = {};
    mma_body<false>(A, Bv, SEQ, DIM, rowBase, colBase, acc);

    const int lane = threadIdx.x & 31;
    const int wid  = threadIdx.x >> 5;
    const int gid  = lane >> 2, tig = lane & 3;
    const int wm   = (wid & 1) * 64, wn = (wid >> 1) * 32;

    #pragma unroll
    for (int nt = 0; nt < 4; nt++) {
        const int col = colBase + wn + nt * 8 + 2 * tig;
        #pragma unroll
        for (int mt = 0; mt < 4; mt++) {
            const int row0 = rowBase + wm + mt * 16 + gid;
            float2 q0 = *(const float2*)(Q + (size_t)row0 * DIM + col);
            float2 q1 = *(const float2*)(Q + (size_t)(row0 + 8) * DIM + col);
            float2 v0 = make_float2(acc[mt][nt][0] + q0.x, acc[mt][nt][1] + q0.y);
            float2 v1 = make_float2(acc[mt][nt][2] + q1.x, acc[mt][nt][3] + q1.y);
            *(float2*)(C + (size_t)row0 * DIM + col)       = v0;
            *(float2*)(C + (size_t)(row0 + 8) * DIM + col) = v1;
        }
    }
}

// ---------------- launch ----------------
extern "C" void kernel_launch(void* const* d_in, const int* in_sizes, int n_in,
                              void* d_out, int out_size)
{
    const float* x  = (const float*)d_in[0];
    const float* Wq = (const float*)d_in[1];
    const float* bq = (const float*)d_in[2];
    const float* Wk = (const float*)d_in[3];
    const float* bk = (const float*)d_in[4];
    const float* Wv = (const float*)d_in[5];
    const float* bv = (const float*)d_in[6];
    float* outp = (float*)d_out;

    // 1. masks
    mask_kernel<<<MTOT, 256>>>(x);

    // 2. QKV projections (z = q/k/v)
    {
        dim3 grid(DIM / BN, MTOT / BM, 3);
        qkv_kernel<<<grid, 256>>>(x, Wq, bq, Wk, bk, Wv, bv);
    }

    // 3. scores = q k^T / 32, key-masked
    {
        dim3 grid(SEQ / BN, SEQ / BM, BATCH);
        scores_kernel<<<grid, 256>>>();
    }

    // 4. softmax + query-mask scaling
    softmax_kernel<<<MTOT, 256>>>();

    // 5. out = attn v + q
    {
        dim3 grid(DIM / BN, SEQ / BM, BATCH);
        out_kernel<<<grid, 256>>>(outp);
    }
}